// round 13
// baseline (speedup 1.0000x reference)
#include <cuda_runtime.h>
#include <cuda_fp16.h>
#include <cstdint>

#define BSZ 2
#define NQ 10000
#define EDIM 256
#define NH 8
#define NL 4
#define NP 8
#define DH 32
#define LEN_VAL 13294
#define NOA 768            // fused off(512) + attn(256) output width

// ---------------- scratch (device globals: allocation-free) ----------------
// v16 layout: [b][h][pos][d] (d=32), +64 pad halfs for the x-pair overfetch
__device__ __half g_v16[(size_t)BSZ * NH * LEN_VAL * DH + 64];
__device__ __half g_a16[(size_t)BSZ * LEN_VAL * EDIM];   // raw value (fp16)
__device__ __half g_q16[(size_t)BSZ * NQ * EDIM];        // q = query + pos (fp16)
__device__ float  g_offattn[(size_t)BSZ * NQ * NOA];     // [off 512 | attn 256]
__device__ __half g_mid16[(size_t)BSZ * NQ * EDIM];      // sampling result (fp16)
__device__ float  g_bias_oa[NOA];

// fp16 weights [K][N], concatenated: [W_val 256x256][W_oa 256x768][W_out 256x256]
#define WOFF_VAL  0
#define WOFF_OA   65536
#define WOFF_OUT  262144
#define WTOTAL    327680
__device__ __half g_W16[WTOTAL];

#define N_VAL_ELEM (BSZ * LEN_VAL * EDIM)   // 6806528
#define N_Q_ELEM   (BSZ * NQ * EDIM)        // 5120000
#define NV4 (N_VAL_ELEM / 4)
#define NQ4 (N_Q_ELEM / 4)
#define PREP_THREADS (NV4 + NQ4 + WTOTAL)

__constant__ int c_Hs[NL]    = {100, 50, 25, 13};
__constant__ int c_Ws[NL]    = {100, 50, 25, 13};
__constant__ int c_start[NL] = {0, 10000, 12500, 13125};

// ---------------- helpers ----------------
__device__ __forceinline__ void ldm_x4(uint32_t& r0, uint32_t& r1, uint32_t& r2, uint32_t& r3,
                                       uint32_t addr) {
    asm volatile("ldmatrix.sync.aligned.m8n8.x4.shared.b16 {%0,%1,%2,%3}, [%4];"
                 : "=r"(r0), "=r"(r1), "=r"(r2), "=r"(r3) : "r"(addr));
}

__device__ __forceinline__ void ldm_x4_trans(uint32_t& r0, uint32_t& r1, uint32_t& r2, uint32_t& r3,
                                             uint32_t addr) {
    asm volatile("ldmatrix.sync.aligned.m8n8.x4.trans.shared.b16 {%0,%1,%2,%3}, [%4];"
                 : "=r"(r0), "=r"(r1), "=r"(r2), "=r"(r3) : "r"(addr));
}

__device__ __forceinline__ void mma_f16(float* d, const uint32_t* a, const uint32_t* b) {
    asm volatile("mma.sync.aligned.m16n8k16.row.col.f32.f16.f16.f32 "
                 "{%0,%1,%2,%3},{%4,%5,%6,%7},{%8,%9},{%0,%1,%2,%3};"
                 : "+f"(d[0]), "+f"(d[1]), "+f"(d[2]), "+f"(d[3])
                 : "r"(a[0]), "r"(a[1]), "r"(a[2]), "r"(a[3]), "r"(b[0]), "r"(b[1]));
}

__device__ __forceinline__ void cp_async16(uint32_t dst, const void* src, bool pred) {
    int sz = pred ? 16 : 0;
    asm volatile("cp.async.cg.shared.global [%0], [%1], 16, %2;\n"
                 :: "r"(dst), "l"(src), "r"(sz));
}
#define CP_COMMIT() asm volatile("cp.async.commit_group;\n" ::)
#define CP_WAIT(N)  asm volatile("cp.async.wait_group %0;\n" :: "n"(N))

__device__ __forceinline__ void store2(float* p, float a, float b) {
    *(float2*)p = make_float2(a, b);
}
__device__ __forceinline__ void store2(__half* p, float a, float b) {
    *(__half2*)p = __floats2half2_rn(a, b);
}

// ---------------- fused prep kernel (vectorized) ----------------
__global__ void prep_kernel(const float4* __restrict__ value,
                            const float4* __restrict__ query,
                            const float4* __restrict__ qpos,
                            const float* __restrict__ W_val,
                            const float* __restrict__ W_off,
                            const float* __restrict__ W_attn,
                            const float* __restrict__ W_out,
                            const float* __restrict__ b_off,
                            const float* __restrict__ b_attn) {
    int i = blockIdx.x * blockDim.x + threadIdx.x;
    if (i < NV4) {
        float4 v = value[i];
        ((__half2*)g_a16)[i * 2]     = __floats2half2_rn(v.x, v.y);
        ((__half2*)g_a16)[i * 2 + 1] = __floats2half2_rn(v.z, v.w);
    } else if (i < NV4 + NQ4) {
        int j = i - NV4;
        float4 a = query[j], b = qpos[j];
        ((__half2*)g_q16)[j * 2]     = __floats2half2_rn(a.x + b.x, a.y + b.y);
        ((__half2*)g_q16)[j * 2 + 1] = __floats2half2_rn(a.z + b.z, a.w + b.w);
    } else if (i < PREP_THREADS) {
        int j = i - NV4 - NQ4;
        float x;
        if (j < WOFF_OA) {
            x = W_val[j];
        } else if (j < WOFF_OUT) {
            int k = j - WOFF_OA;
            int r = k / NOA, c = k - r * NOA;
            x = (c < 512) ? W_off[r * 512 + c] : W_attn[r * 256 + (c - 512)];
        } else {
            x = W_out[j - WOFF_OUT];
        }
        g_W16[j] = __float2half(x);
        if (j < NOA) g_bias_oa[j] = (j < 512) ? b_off[j] : b_attn[j - 512];
    }
}

// ---------------- fp16 tensor-core GEMM, cp.async, BK=64, 3 stages ----------------
// BM=128, BN=64, BK=64, 256 threads (8 warps 4x2, warp tile 32x32), 2 CTAs/SM.
#define SA_STRIDE 72                      // halfs per A row (64 + 8 pad)
#define SB_STRIDE 72                      // halfs per B row (64 + 8 pad)
#define SA_BYTES  (128 * SA_STRIDE * 2)   // 18432
#define SB_BYTES  (64 * SB_STRIDE * 2)    // 9216
#define NSTAGE 3
#define OFF_A 0
#define OFF_B (NSTAGE * SA_BYTES)
#define GEMM_SMEM (NSTAGE * (SA_BYTES + SB_BYTES))   // 82944

// PERM=true: C is __half in [b][h][pos][d] layout (value projection)
template <typename TOut, bool PERM>
__global__ void __launch_bounds__(256, 2)
gemm_f16_kernel(const __half* __restrict__ A,
                const __half* __restrict__ B,
                const float* __restrict__ bias,
                TOut* __restrict__ C,
                int M, int N) {
    extern __shared__ char smem_raw[];
    const uint32_t sbase = (uint32_t)__cvta_generic_to_shared(smem_raw);

    const int tid  = threadIdx.x;
    const int lane = tid & 31;
    const int wid  = tid >> 5;
    const int warp_m = wid & 3;       // 0..3
    const int warp_n = wid >> 2;      // 0..1

    const int row0 = blockIdx.y * 128;
    const int col0 = blockIdx.x * 64;

    // A: 128 rows x 64 halfs; thread loads 4 x 16B (32-half span)
    const int a_row = tid >> 1;              // 0..127
    const int a_c32 = (tid & 1) * 32;        // 0 or 32 halfs
    // B: 64 k-rows x 64 halfs; thread loads 2 x 16B (16-half span)
    const int b_kr  = tid >> 2;              // 0..63
    const int b_c16 = (tid & 3) * 16;        // 0,16,32,48 halfs

    const bool a_pred = (row0 + a_row) < M;
    const __half* srcA = A + (size_t)(row0 + a_row) * 256 + a_c32;
    const __half* srcB = B + (size_t)b_kr * N + col0 + b_c16;

    const uint32_t dA = sbase + OFF_A + a_row * (SA_STRIDE * 2) + a_c32 * 2;
    const uint32_t dB = sbase + OFF_B + b_kr * (SB_STRIDE * 2) + b_c16 * 2;

#define ISSUE(J)                                                             \
    {                                                                        \
        int s = (J) % NSTAGE;                                                \
        int k0 = (J) * 64;                                                   \
        cp_async16(dA + s * SA_BYTES,      srcA + k0,      a_pred);          \
        cp_async16(dA + s * SA_BYTES + 16, srcA + k0 + 8,  a_pred);          \
        cp_async16(dA + s * SA_BYTES + 32, srcA + k0 + 16, a_pred);          \
        cp_async16(dA + s * SA_BYTES + 48, srcA + k0 + 24, a_pred);          \
        cp_async16(dB + s * SB_BYTES,      srcB + (size_t)k0 * N,     true); \
        cp_async16(dB + s * SB_BYTES + 16, srcB + (size_t)k0 * N + 8, true); \
    }

    ISSUE(0); CP_COMMIT();
    ISSUE(1); CP_COMMIT();

    float acc[2][4][4];
#pragma unroll
    for (int mt = 0; mt < 2; mt++)
#pragma unroll
        for (int nb = 0; nb < 4; nb++)
#pragma unroll
            for (int j = 0; j < 4; j++) acc[mt][nb][j] = 0.f;

    const int NK = 4;
    for (int it = 0; it < NK; ++it) {
        CP_WAIT(1);
        __syncthreads();
        if (it + 2 < NK) ISSUE(it + 2);
        CP_COMMIT();

        const int s = it % NSTAGE;
        const uint32_t aB = sbase + OFF_A + s * SA_BYTES;
        const uint32_t bB = sbase + OFF_B + s * SB_BYTES;

#pragma unroll
        for (int ks = 0; ks < 4; ks++) {
            uint32_t af[2][4], bf[4][2];
#pragma unroll
            for (int mt = 0; mt < 2; mt++) {
                int row = warp_m * 32 + mt * 16 + (lane & 15);
                int col = ks * 16 + ((lane >> 4) << 3);
                ldm_x4(af[mt][0], af[mt][1], af[mt][2], af[mt][3],
                       aB + row * (SA_STRIDE * 2) + col * 2);
            }
#pragma unroll
            for (int g = 0; g < 2; g++) {
                int kk = ks * 16 + ((lane >> 3) & 1) * 8 + (lane & 7);
                int nn = warp_n * 32 + g * 16 + ((lane >> 4) & 1) * 8;
                uint32_t r0, r1, r2, r3;
                ldm_x4_trans(r0, r1, r2, r3, bB + kk * (SB_STRIDE * 2) + nn * 2);
                bf[2 * g][0] = r0;     bf[2 * g][1] = r1;
                bf[2 * g + 1][0] = r2; bf[2 * g + 1][1] = r3;
            }
#pragma unroll
            for (int mt = 0; mt < 2; mt++)
#pragma unroll
                for (int nb = 0; nb < 4; nb++)
                    mma_f16(acc[mt][nb], af[mt], bf[nb]);
        }
    }
#undef ISSUE

#pragma unroll
    for (int mt = 0; mt < 2; mt++) {
#pragma unroll
        for (int nb = 0; nb < 4; nb++) {
            int gn = col0 + warp_n * 32 + nb * 8 + (lane & 3) * 2;
            float b0 = bias[gn], b1 = bias[gn + 1];
            int gm0 = row0 + warp_m * 32 + mt * 16 + (lane >> 2);
            int gm1 = gm0 + 8;
            if (PERM) {
                int hh = gn >> 5, dd = gn & 31;
                if (gm0 < M) {
                    int bb = gm0 >= LEN_VAL;
                    int pos = gm0 - bb * LEN_VAL;
                    __half* dst = (__half*)C + ((size_t)(bb * NH + hh) * LEN_VAL + pos) * DH + dd;
                    store2(dst, acc[mt][nb][0] + b0, acc[mt][nb][1] + b1);
                }
                if (gm1 < M) {
                    int bb = gm1 >= LEN_VAL;
                    int pos = gm1 - bb * LEN_VAL;
                    __half* dst = (__half*)C + ((size_t)(bb * NH + hh) * LEN_VAL + pos) * DH + dd;
                    store2(dst, acc[mt][nb][2] + b0, acc[mt][nb][3] + b1);
                }
            } else {
                if (gm0 < M) store2(C + (size_t)gm0 * N + gn,
                                    acc[mt][nb][0] + b0, acc[mt][nb][1] + b1);
                if (gm1 < M) store2(C + (size_t)gm1 * N + gn,
                                    acc[mt][nb][2] + b0, acc[mt][nb][3] + b1);
            }
        }
    }
}

// ---------------- deformable sampling v4 (R10 exact) ----------------
__global__ void __launch_bounds__(256)
sample_kernel(const float* __restrict__ ref) {
    __shared__ int2   s_ad[8][32];
    __shared__ float4 s_w[8][32];

    const int wlocal = threadIdx.x >> 5;
    const int lane   = threadIdx.x & 31;
    const int gw = blockIdx.x * 8 + wlocal;

    const int h = gw & (NH - 1);
    const int n = (gw >> 3) % NQ;
    const int b = gw / (NQ * NH);
    const long qrow = (long)b * NQ + n;
    const float* oa = g_offattn + qrow * NOA;

    // ---- phase 1 ----
    {
        int l = lane >> 3;
        int Hs = c_Hs[l], Ws = c_Ws[l];
        int ocol = ((h * NL + l) * NP + (lane & 7)) * 2;
        float ox = oa[ocol];
        float oy = oa[ocol + 1];
        float rx = ref[(qrow * NL + l) * 2 + 0];
        float ry = ref[(qrow * NL + l) * 2 + 1];

        float x = rx * (float)Ws + ox - 0.5f;
        float y = ry * (float)Hs + oy - 0.5f;

        float fx0 = floorf(x), fy0 = floorf(y);
        int x0 = (int)fx0, y0 = (int)fy0;
        float wx1 = x - fx0, wy1f = y - fy0;
        float wx0 = 1.f - wx1, wy0f = 1.f - wy1f;

        float logit = oa[512 + h * DH + lane];
        float m = logit;
#pragma unroll
        for (int o = 16; o; o >>= 1) m = fmaxf(m, __shfl_xor_sync(0xFFFFFFFFu, m, o));
        float ex = __expf(logit - m);
        float s = ex;
#pragma unroll
        for (int o = 16; o; o >>= 1) s += __shfl_xor_sync(0xFFFFFFFFu, s, o);
        float aw = ex / s;

        int x1 = x0 + 1, y1 = y0 + 1;
        bool vy0 = (y0 >= 0) && (y0 < Hs);
        bool vy1 = (y1 >= 0) && (y1 < Hs);

        int xb = min(max(x0, 0), Ws - 2);
        int pA = xb, pB = xb + 1;
        float wxA = (pA == x0 ? wx0 : 0.f) + (pA == x1 ? wx1 : 0.f);
        float wxB = (pB == x0 ? wx0 : 0.f) + (pB == x1 ? wx1 : 0.f);

        float wy0 = vy0 ? aw * wy0f : 0.f;
        float wy1 = vy1 ? aw * wy1f : 0.f;
        int py0 = vy0 ? y0 : 0;
        int py1 = vy1 ? y1 : 0;

        int base = ((b * NH + h) * LEN_VAL + c_start[l]) * DH;
        int a0 = base + (py0 * Ws + xb) * DH;
        int a1 = base + (py1 * Ws + xb) * DH;

        s_ad[wlocal][lane] = make_int2(a0, a1);
        s_w[wlocal][lane]  = make_float4(wy0 * wxA, wy0 * wxB, wy1 * wxA, wy1 * wxB);
    }
    __syncwarp();

    // ---- phase 2 ----
    const int slot = lane >> 3;
    const int half = (lane >> 2) & 1;
    const int q    = lane & 3;
    const int sub  = half * DH + q * 8;
    const __half* vb = g_v16;

    float2 acc[4];
#pragma unroll
    for (int j = 0; j < 4; j++) acc[j] = make_float2(0.f, 0.f);

#pragma unroll
    for (int it = 0; it < 8; it++) {
        int sIdx = it * 4 + slot;
        int2   ad = s_ad[wlocal][sIdx];
        float4 ww = s_w[wlocal][sIdx];
        float w0 = half ? ww.y : ww.x;
        float w1 = half ? ww.w : ww.z;

        uint4 u0 = *(const uint4*)(vb + ad.x + sub);
        uint4 u1 = *(const uint4*)(vb + ad.y + sub);
        float2 f;
        f = __half22float2(*(__half2*)&u0.x); acc[0].x = fmaf(w0, f.x, acc[0].x); acc[0].y = fmaf(w0, f.y, acc[0].y);
        f = __half22float2(*(__half2*)&u0.y); acc[1].x = fmaf(w0, f.x, acc[1].x); acc[1].y = fmaf(w0, f.y, acc[1].y);
        f = __half22float2(*(__half2*)&u0.z); acc[2].x = fmaf(w0, f.x, acc[2].x); acc[2].y = fmaf(w0, f.y, acc[2].y);
        f = __half22float2(*(__half2*)&u0.w); acc[3].x = fmaf(w0, f.x, acc[3].x); acc[3].y = fmaf(w0, f.y, acc[3].y);
        f = __half22float2(*(__half2*)&u1.x); acc[0].x = fmaf(w1, f.x, acc[0].x); acc[0].y = fmaf(w1, f.y, acc[0].y);
        f = __half22float2(*(__half2*)&u1.y); acc[1].x = fmaf(w1, f.x, acc[1].x); acc[1].y = fmaf(w1, f.y, acc[1].y);
        f = __half22float2(*(__half2*)&u1.z); acc[2].x = fmaf(w1, f.x, acc[2].x); acc[2].y = fmaf(w1, f.y, acc[2].y);
        f = __half22float2(*(__half2*)&u1.w); acc[3].x = fmaf(w1, f.x, acc[3].x); acc[3].y = fmaf(w1, f.y, acc[3].y);
    }

#pragma unroll
    for (int o = 4; o <= 16; o <<= 1) {
#pragma unroll
        for (int j = 0; j < 4; j++) {
            acc[j].x += __shfl_xor_sync(0xFFFFFFFFu, acc[j].x, o);
            acc[j].y += __shfl_xor_sync(0xFFFFFFFFu, acc[j].y, o);
        }
    }

    if (lane < 4) {
        __align__(16) __half2 outv[4];
#pragma unroll
        for (int j = 0; j < 4; j++) outv[j] = __floats2half2_rn(acc[j].x, acc[j].y);
        size_t midx = qrow * EDIM + h * DH + lane * 8;
        *(uint4*)(g_mid16 + midx) = *(uint4*)outv;
    }
}

// ---------------- launch (R10 schedule) ----------------
extern "C" void kernel_launch(void* const* d_in, const int* in_sizes, int n_in,
                              void* d_out, int out_size) {
    const float* query   = (const float*)d_in[0];
    const float* value   = (const float*)d_in[1];
    const float* qpos    = (const float*)d_in[2];
    const float* refpts  = (const float*)d_in[3];
    const float* W_off   = (const float*)d_in[5];
    const float* b_off   = (const float*)d_in[6];
    const float* W_attn  = (const float*)d_in[7];
    const float* b_attn  = (const float*)d_in[8];
    const float* W_val   = (const float*)d_in[9];
    const float* b_val   = (const float*)d_in[10];
    const float* W_out   = (const float*)d_in[11];
    const float* b_out   = (const float*)d_in[12];
    float* out = (float*)d_out;

    __half *w16, *q16, *a16, *v16, *mid16;
    float *voa, *boa;
    cudaGetSymbolAddress((void**)&w16, g_W16);
    cudaGetSymbolAddress((void**)&q16, g_q16);
    cudaGetSymbolAddress((void**)&a16, g_a16);
    cudaGetSymbolAddress((void**)&v16, g_v16);
    cudaGetSymbolAddress((void**)&mid16, g_mid16);
    cudaGetSymbolAddress((void**)&voa, g_offattn);
    cudaGetSymbolAddress((void**)&boa, g_bias_oa);

    static bool init_done = false;
    static cudaStream_t s2;
    static cudaEvent_t evPrep, evVal;
    if (!init_done) {
        cudaFuncSetAttribute((const void*)gemm_f16_kernel<float, false>,
                             cudaFuncAttributeMaxDynamicSharedMemorySize, GEMM_SMEM);
        cudaFuncSetAttribute((const void*)gemm_f16_kernel<__half, true>,
                             cudaFuncAttributeMaxDynamicSharedMemorySize, GEMM_SMEM);
        cudaStreamCreateWithFlags(&s2, cudaStreamNonBlocking);
        cudaEventCreateWithFlags(&evPrep, cudaEventDisableTiming);
        cudaEventCreateWithFlags(&evVal, cudaEventDisableTiming);
        init_done = true;
    }

    // 0) fused prep (vectorized)
    prep_kernel<<<(PREP_THREADS + 255) / 256, 256>>>(
        (const float4*)value, (const float4*)query, (const float4*)qpos,
        W_val, W_off, W_attn, W_out, b_off, b_attn);

    // fork: value-projection chain on s2
    cudaEventRecord(evPrep, 0);
    cudaStreamWaitEvent(s2, evPrep, 0);

    // 1a) [s2] v = value @ W_val + b_val -> fp16 in [b][h][pos][d] layout
    {
        int M = BSZ * LEN_VAL, N = EDIM;
        dim3 grid(N / 64, (M + 127) / 128);
        gemm_f16_kernel<__half, true><<<grid, 256, GEMM_SMEM, s2>>>(
            a16, w16 + WOFF_VAL, b_val, v16, M, N);
    }
    cudaEventRecord(evVal, s2);

    // 1b) [default] [off|attn] = q @ W_oa + b_oa (N = 768)
    {
        int M = BSZ * NQ, N = NOA;
        dim3 grid(N / 64, (M + 127) / 128);
        gemm_f16_kernel<float, false><<<grid, 256, GEMM_SMEM>>>(
            q16, w16 + WOFF_OA, boa, voa, M, N);
    }

    // join
    cudaStreamWaitEvent(0, evVal, 0);

    // 2) deformable sampling -> g_mid16
    {
        int groups = BSZ * NQ * NH;              // 160000
        sample_kernel<<<groups / 8, 256>>>(refpts);
    }
    // 3) out = mid @ W_out + b_out
    {
        int M = BSZ * NQ, N = EDIM;
        dim3 grid(N / 64, (M + 127) / 128);
        gemm_f16_kernel<float, false><<<grid, 256, GEMM_SMEM>>>(
            mid16, w16 + WOFF_OUT, b_out, out, M, N);
    }
}

// round 14
// speedup vs baseline: 1.0261x; 1.0261x over previous
#include <cuda_runtime.h>
#include <cuda_fp16.h>
#include <cstdint>

#define BSZ 2
#define NQ 10000
#define EDIM 256
#define NH 8
#define NL 4
#define NP 8
#define DH 32
#define LEN_VAL 13294
#define NOA 768            // fused off(512) + attn(256) output width

// ---------------- scratch (device globals: allocation-free) ----------------
// v16 layout: [b][h][pos][d] (d=32), +64 pad halfs for the x-pair overfetch
__device__ __half g_v16[(size_t)BSZ * NH * LEN_VAL * DH + 64];
__device__ __half g_a16[(size_t)BSZ * LEN_VAL * EDIM];   // raw value (fp16)
__device__ __half g_q16[(size_t)BSZ * NQ * EDIM];        // q = query + pos (fp16)
__device__ float  g_offattn[(size_t)BSZ * NQ * NOA];     // [off 512 | attn 256]
__device__ __half g_mid16[(size_t)BSZ * NQ * EDIM];      // sampling result (fp16)
__device__ float  g_bias_oa[NOA];

// fp16 weights [K][N], concatenated: [W_val 256x256][W_oa 256x768][W_out 256x256]
#define WOFF_VAL  0
#define WOFF_OA   65536
#define WOFF_OUT  262144
#define WTOTAL    327680
__device__ __half g_W16[WTOTAL];

#define N_VAL_ELEM (BSZ * LEN_VAL * EDIM)   // 6806528
#define N_Q_ELEM   (BSZ * NQ * EDIM)        // 5120000
#define NV4 (N_VAL_ELEM / 4)
#define NQ4 (N_Q_ELEM / 4)
#define PREP_THREADS (NV4 + NQ4 + WTOTAL)

__constant__ int c_Hs[NL]    = {100, 50, 25, 13};
__constant__ int c_Ws[NL]    = {100, 50, 25, 13};
__constant__ int c_start[NL] = {0, 10000, 12500, 13125};

// ---------------- helpers ----------------
__device__ __forceinline__ void ldm_x4(uint32_t& r0, uint32_t& r1, uint32_t& r2, uint32_t& r3,
                                       uint32_t addr) {
    asm volatile("ldmatrix.sync.aligned.m8n8.x4.shared.b16 {%0,%1,%2,%3}, [%4];"
                 : "=r"(r0), "=r"(r1), "=r"(r2), "=r"(r3) : "r"(addr));
}

__device__ __forceinline__ void ldm_x4_trans(uint32_t& r0, uint32_t& r1, uint32_t& r2, uint32_t& r3,
                                             uint32_t addr) {
    asm volatile("ldmatrix.sync.aligned.m8n8.x4.trans.shared.b16 {%0,%1,%2,%3}, [%4];"
                 : "=r"(r0), "=r"(r1), "=r"(r2), "=r"(r3) : "r"(addr));
}

__device__ __forceinline__ void mma_f16(float* d, const uint32_t* a, const uint32_t* b) {
    asm volatile("mma.sync.aligned.m16n8k16.row.col.f32.f16.f16.f32 "
                 "{%0,%1,%2,%3},{%4,%5,%6,%7},{%8,%9},{%0,%1,%2,%3};"
                 : "+f"(d[0]), "+f"(d[1]), "+f"(d[2]), "+f"(d[3])
                 : "r"(a[0]), "r"(a[1]), "r"(a[2]), "r"(a[3]), "r"(b[0]), "r"(b[1]));
}

__device__ __forceinline__ void cp_async16(uint32_t dst, const void* src, bool pred) {
    int sz = pred ? 16 : 0;
    asm volatile("cp.async.cg.shared.global [%0], [%1], 16, %2;\n"
                 :: "r"(dst), "l"(src), "r"(sz));
}
#define CP_COMMIT() asm volatile("cp.async.commit_group;\n" ::)
#define CP_WAIT(N)  asm volatile("cp.async.wait_group %0;\n" :: "n"(N))

__device__ __forceinline__ void store2(float* p, float a, float b) {
    *(float2*)p = make_float2(a, b);
}
__device__ __forceinline__ void store2(__half* p, float a, float b) {
    *(__half2*)p = __floats2half2_rn(a, b);
}

// ---------------- fused prep kernel (vectorized) ----------------
__global__ void prep_kernel(const float4* __restrict__ value,
                            const float4* __restrict__ query,
                            const float4* __restrict__ qpos,
                            const float* __restrict__ W_val,
                            const float* __restrict__ W_off,
                            const float* __restrict__ W_attn,
                            const float* __restrict__ W_out,
                            const float* __restrict__ b_off,
                            const float* __restrict__ b_attn) {
    int i = blockIdx.x * blockDim.x + threadIdx.x;
    if (i < NV4) {
        float4 v = value[i];
        ((__half2*)g_a16)[i * 2]     = __floats2half2_rn(v.x, v.y);
        ((__half2*)g_a16)[i * 2 + 1] = __floats2half2_rn(v.z, v.w);
    } else if (i < NV4 + NQ4) {
        int j = i - NV4;
        float4 a = query[j], b = qpos[j];
        ((__half2*)g_q16)[j * 2]     = __floats2half2_rn(a.x + b.x, a.y + b.y);
        ((__half2*)g_q16)[j * 2 + 1] = __floats2half2_rn(a.z + b.z, a.w + b.w);
    } else if (i < PREP_THREADS) {
        int j = i - NV4 - NQ4;
        float x;
        if (j < WOFF_OA) {
            x = W_val[j];
        } else if (j < WOFF_OUT) {
            int k = j - WOFF_OA;
            int r = k / NOA, c = k - r * NOA;
            x = (c < 512) ? W_off[r * 512 + c] : W_attn[r * 256 + (c - 512)];
        } else {
            x = W_out[j - WOFF_OUT];
        }
        g_W16[j] = __float2half(x);
        if (j < NOA) g_bias_oa[j] = (j < 512) ? b_off[j] : b_attn[j - 512];
    }
}

// ---------------- fp16 tensor-core GEMM, cp.async 4-stage (R10 exact) ----------------
// BM=128, BN=64, BK=32, 256 threads (8 warps 4x2, warp tile 32x32), 2 CTAs/SM.
#define SA_STRIDE 40
#define SB_STRIDE 72
#define SA_BYTES  (128 * SA_STRIDE * 2)   // 10240
#define SB_BYTES  (32 * SB_STRIDE * 2)    // 4608
#define NSTAGE 4
#define OFF_A 0
#define OFF_B (NSTAGE * SA_BYTES)
#define GEMM_SMEM (NSTAGE * (SA_BYTES + SB_BYTES))   // 59392

// PERM=true: C is __half in [b][h][pos][d] layout (value projection)
template <typename TOut, bool PERM>
__global__ void __launch_bounds__(256, 2)
gemm_f16_kernel(const __half* __restrict__ A,
                const __half* __restrict__ B,
                const float* __restrict__ bias,
                TOut* __restrict__ C,
                int M, int N) {
    extern __shared__ char smem_raw[];
    const uint32_t sbase = (uint32_t)__cvta_generic_to_shared(smem_raw);

    const int tid  = threadIdx.x;
    const int lane = tid & 31;
    const int wid  = tid >> 5;
    const int warp_m = wid & 3;       // 0..3
    const int warp_n = wid >> 2;      // 0..1

    const int row0 = blockIdx.y * 128;
    const int col0 = blockIdx.x * 64;

    const int a_row = tid >> 1;             // 0..127
    const int a_c16 = (tid & 1) * 16;       // 0 or 16 halfs
    const int b_kr  = tid >> 3;             // 0..31
    const int b_c8  = (tid & 7) * 8;        // 0..56

    const bool a_pred = (row0 + a_row) < M;
    const __half* srcA = A + (size_t)(row0 + a_row) * 256 + a_c16;
    const __half* srcB = B + (size_t)b_kr * N + col0 + b_c8;

    const uint32_t dA = sbase + OFF_A + a_row * (SA_STRIDE * 2) + a_c16 * 2;
    const uint32_t dB = sbase + OFF_B + b_kr * (SB_STRIDE * 2) + b_c8 * 2;

#define ISSUE(J)                                                             \
    {                                                                        \
        int s = (J) & (NSTAGE - 1);                                          \
        int k0 = (J) * 32;                                                   \
        cp_async16(dA + s * SA_BYTES, srcA + k0, a_pred);                    \
        cp_async16(dA + s * SA_BYTES + 16, srcA + k0 + 8, a_pred);           \
        cp_async16(dB + s * SB_BYTES, srcB + (size_t)k0 * N, true);          \
    }

    ISSUE(0); CP_COMMIT();
    ISSUE(1); CP_COMMIT();
    ISSUE(2); CP_COMMIT();

    float acc[2][4][4];
#pragma unroll
    for (int mt = 0; mt < 2; mt++)
#pragma unroll
        for (int nb = 0; nb < 4; nb++)
#pragma unroll
            for (int j = 0; j < 4; j++) acc[mt][nb][j] = 0.f;

    const int NK = 8;
    for (int it = 0; it < NK; ++it) {
        CP_WAIT(2);
        __syncthreads();
        if (it + 3 < NK) ISSUE(it + 3);
        CP_COMMIT();

        const int s = it & (NSTAGE - 1);
        const uint32_t aB = sbase + OFF_A + s * SA_BYTES;
        const uint32_t bB = sbase + OFF_B + s * SB_BYTES;

#pragma unroll
        for (int ks = 0; ks < 2; ks++) {
            uint32_t af[2][4], bf[4][2];
#pragma unroll
            for (int mt = 0; mt < 2; mt++) {
                int row = warp_m * 32 + mt * 16 + (lane & 15);
                int col = ks * 16 + ((lane >> 4) << 3);
                ldm_x4(af[mt][0], af[mt][1], af[mt][2], af[mt][3],
                       aB + row * (SA_STRIDE * 2) + col * 2);
            }
#pragma unroll
            for (int g = 0; g < 2; g++) {
                int kk = ks * 16 + ((lane >> 3) & 1) * 8 + (lane & 7);
                int nn = warp_n * 32 + g * 16 + ((lane >> 4) & 1) * 8;
                uint32_t r0, r1, r2, r3;
                ldm_x4_trans(r0, r1, r2, r3, bB + kk * (SB_STRIDE * 2) + nn * 2);
                bf[2 * g][0] = r0;     bf[2 * g][1] = r1;
                bf[2 * g + 1][0] = r2; bf[2 * g + 1][1] = r3;
            }
#pragma unroll
            for (int mt = 0; mt < 2; mt++)
#pragma unroll
                for (int nb = 0; nb < 4; nb++)
                    mma_f16(acc[mt][nb], af[mt], bf[nb]);
        }
    }
#undef ISSUE

#pragma unroll
    for (int mt = 0; mt < 2; mt++) {
#pragma unroll
        for (int nb = 0; nb < 4; nb++) {
            int gn = col0 + warp_n * 32 + nb * 8 + (lane & 3) * 2;
            float b0 = bias[gn], b1 = bias[gn + 1];
            int gm0 = row0 + warp_m * 32 + mt * 16 + (lane >> 2);
            int gm1 = gm0 + 8;
            if (PERM) {
                int hh = gn >> 5, dd = gn & 31;
                if (gm0 < M) {
                    int bb = gm0 >= LEN_VAL;
                    int pos = gm0 - bb * LEN_VAL;
                    __half* dst = (__half*)C + ((size_t)(bb * NH + hh) * LEN_VAL + pos) * DH + dd;
                    store2(dst, acc[mt][nb][0] + b0, acc[mt][nb][1] + b1);
                }
                if (gm1 < M) {
                    int bb = gm1 >= LEN_VAL;
                    int pos = gm1 - bb * LEN_VAL;
                    __half* dst = (__half*)C + ((size_t)(bb * NH + hh) * LEN_VAL + pos) * DH + dd;
                    store2(dst, acc[mt][nb][2] + b0, acc[mt][nb][3] + b1);
                }
            } else {
                if (gm0 < M) store2(C + (size_t)gm0 * N + gn,
                                    acc[mt][nb][0] + b0, acc[mt][nb][1] + b1);
                if (gm1 < M) store2(C + (size_t)gm1 * N + gn,
                                    acc[mt][nb][2] + b0, acc[mt][nb][3] + b1);
            }
        }
    }
}

// ---------------- deformable sampling v4 (R10 exact + block offset) ----------------
__global__ void __launch_bounds__(256)
sample_kernel(const float* __restrict__ ref, int blkoff) {
    __shared__ int2   s_ad[8][32];
    __shared__ float4 s_w[8][32];

    const int wlocal = threadIdx.x >> 5;
    const int lane   = threadIdx.x & 31;
    const int gw = (blockIdx.x + blkoff) * 8 + wlocal;

    const int h = gw & (NH - 1);
    const int n = (gw >> 3) % NQ;
    const int b = gw / (NQ * NH);
    const long qrow = (long)b * NQ + n;
    const float* oa = g_offattn + qrow * NOA;

    // ---- phase 1 ----
    {
        int l = lane >> 3;
        int Hs = c_Hs[l], Ws = c_Ws[l];
        int ocol = ((h * NL + l) * NP + (lane & 7)) * 2;
        float ox = oa[ocol];
        float oy = oa[ocol + 1];
        float rx = ref[(qrow * NL + l) * 2 + 0];
        float ry = ref[(qrow * NL + l) * 2 + 1];

        float x = rx * (float)Ws + ox - 0.5f;
        float y = ry * (float)Hs + oy - 0.5f;

        float fx0 = floorf(x), fy0 = floorf(y);
        int x0 = (int)fx0, y0 = (int)fy0;
        float wx1 = x - fx0, wy1f = y - fy0;
        float wx0 = 1.f - wx1, wy0f = 1.f - wy1f;

        float logit = oa[512 + h * DH + lane];
        float m = logit;
#pragma unroll
        for (int o = 16; o; o >>= 1) m = fmaxf(m, __shfl_xor_sync(0xFFFFFFFFu, m, o));
        float ex = __expf(logit - m);
        float s = ex;
#pragma unroll
        for (int o = 16; o; o >>= 1) s += __shfl_xor_sync(0xFFFFFFFFu, s, o);
        float aw = ex / s;

        int x1 = x0 + 1, y1 = y0 + 1;
        bool vy0 = (y0 >= 0) && (y0 < Hs);
        bool vy1 = (y1 >= 0) && (y1 < Hs);

        int xb = min(max(x0, 0), Ws - 2);
        int pA = xb, pB = xb + 1;
        float wxA = (pA == x0 ? wx0 : 0.f) + (pA == x1 ? wx1 : 0.f);
        float wxB = (pB == x0 ? wx0 : 0.f) + (pB == x1 ? wx1 : 0.f);

        float wy0 = vy0 ? aw * wy0f : 0.f;
        float wy1 = vy1 ? aw * wy1f : 0.f;
        int py0 = vy0 ? y0 : 0;
        int py1 = vy1 ? y1 : 0;

        int base = ((b * NH + h) * LEN_VAL + c_start[l]) * DH;
        int a0 = base + (py0 * Ws + xb) * DH;
        int a1 = base + (py1 * Ws + xb) * DH;

        s_ad[wlocal][lane] = make_int2(a0, a1);
        s_w[wlocal][lane]  = make_float4(wy0 * wxA, wy0 * wxB, wy1 * wxA, wy1 * wxB);
    }
    __syncwarp();

    // ---- phase 2 ----
    const int slot = lane >> 3;
    const int half = (lane >> 2) & 1;
    const int q    = lane & 3;
    const int sub  = half * DH + q * 8;
    const __half* vb = g_v16;

    float2 acc[4];
#pragma unroll
    for (int j = 0; j < 4; j++) acc[j] = make_float2(0.f, 0.f);

#pragma unroll
    for (int it = 0; it < 8; it++) {
        int sIdx = it * 4 + slot;
        int2   ad = s_ad[wlocal][sIdx];
        float4 ww = s_w[wlocal][sIdx];
        float w0 = half ? ww.y : ww.x;
        float w1 = half ? ww.w : ww.z;

        uint4 u0 = *(const uint4*)(vb + ad.x + sub);
        uint4 u1 = *(const uint4*)(vb + ad.y + sub);
        float2 f;
        f = __half22float2(*(__half2*)&u0.x); acc[0].x = fmaf(w0, f.x, acc[0].x); acc[0].y = fmaf(w0, f.y, acc[0].y);
        f = __half22float2(*(__half2*)&u0.y); acc[1].x = fmaf(w0, f.x, acc[1].x); acc[1].y = fmaf(w0, f.y, acc[1].y);
        f = __half22float2(*(__half2*)&u0.z); acc[2].x = fmaf(w0, f.x, acc[2].x); acc[2].y = fmaf(w0, f.y, acc[2].y);
        f = __half22float2(*(__half2*)&u0.w); acc[3].x = fmaf(w0, f.x, acc[3].x); acc[3].y = fmaf(w0, f.y, acc[3].y);
        f = __half22float2(*(__half2*)&u1.x); acc[0].x = fmaf(w1, f.x, acc[0].x); acc[0].y = fmaf(w1, f.y, acc[0].y);
        f = __half22float2(*(__half2*)&u1.y); acc[1].x = fmaf(w1, f.x, acc[1].x); acc[1].y = fmaf(w1, f.y, acc[1].y);
        f = __half22float2(*(__half2*)&u1.z); acc[2].x = fmaf(w1, f.x, acc[2].x); acc[2].y = fmaf(w1, f.y, acc[2].y);
        f = __half22float2(*(__half2*)&u1.w); acc[3].x = fmaf(w1, f.x, acc[3].x); acc[3].y = fmaf(w1, f.y, acc[3].y);
    }

#pragma unroll
    for (int o = 4; o <= 16; o <<= 1) {
#pragma unroll
        for (int j = 0; j < 4; j++) {
            acc[j].x += __shfl_xor_sync(0xFFFFFFFFu, acc[j].x, o);
            acc[j].y += __shfl_xor_sync(0xFFFFFFFFu, acc[j].y, o);
        }
    }

    if (lane < 4) {
        __align__(16) __half2 outv[4];
#pragma unroll
        for (int j = 0; j < 4; j++) outv[j] = __floats2half2_rn(acc[j].x, acc[j].y);
        size_t midx = qrow * EDIM + h * DH + lane * 8;
        *(uint4*)(g_mid16 + midx) = *(uint4*)outv;
    }
}

// ---------------- launch: R10 schedule + tail overlap ----------------
extern "C" void kernel_launch(void* const* d_in, const int* in_sizes, int n_in,
                              void* d_out, int out_size) {
    const float* query   = (const float*)d_in[0];
    const float* value   = (const float*)d_in[1];
    const float* qpos    = (const float*)d_in[2];
    const float* refpts  = (const float*)d_in[3];
    const float* W_off   = (const float*)d_in[5];
    const float* b_off   = (const float*)d_in[6];
    const float* W_attn  = (const float*)d_in[7];
    const float* b_attn  = (const float*)d_in[8];
    const float* W_val   = (const float*)d_in[9];
    const float* b_val   = (const float*)d_in[10];
    const float* W_out   = (const float*)d_in[11];
    const float* b_out   = (const float*)d_in[12];
    float* out = (float*)d_out;

    __half *w16, *q16, *a16, *v16, *mid16;
    float *voa, *boa;
    cudaGetSymbolAddress((void**)&w16, g_W16);
    cudaGetSymbolAddress((void**)&q16, g_q16);
    cudaGetSymbolAddress((void**)&a16, g_a16);
    cudaGetSymbolAddress((void**)&v16, g_v16);
    cudaGetSymbolAddress((void**)&mid16, g_mid16);
    cudaGetSymbolAddress((void**)&voa, g_offattn);
    cudaGetSymbolAddress((void**)&boa, g_bias_oa);

    static bool init_done = false;
    static cudaStream_t s2;
    static cudaEvent_t evPrep, evVal, evSampA, evOutA;
    if (!init_done) {
        cudaFuncSetAttribute((const void*)gemm_f16_kernel<float, false>,
                             cudaFuncAttributeMaxDynamicSharedMemorySize, GEMM_SMEM);
        cudaFuncSetAttribute((const void*)gemm_f16_kernel<__half, true>,
                             cudaFuncAttributeMaxDynamicSharedMemorySize, GEMM_SMEM);
        cudaStreamCreateWithFlags(&s2, cudaStreamNonBlocking);
        cudaEventCreateWithFlags(&evPrep,  cudaEventDisableTiming);
        cudaEventCreateWithFlags(&evVal,   cudaEventDisableTiming);
        cudaEventCreateWithFlags(&evSampA, cudaEventDisableTiming);
        cudaEventCreateWithFlags(&evOutA,  cudaEventDisableTiming);
        init_done = true;
    }

    // 0) fused prep (vectorized)
    prep_kernel<<<(PREP_THREADS + 255) / 256, 256>>>(
        (const float4*)value, (const float4*)query, (const float4*)qpos,
        W_val, W_off, W_attn, W_out, b_off, b_attn);

    // fork: value-projection chain on s2
    cudaEventRecord(evPrep, 0);
    cudaStreamWaitEvent(s2, evPrep, 0);

    // 1a) [s2] v = value @ W_val + b_val -> fp16 in [b][h][pos][d] layout
    {
        int M = BSZ * LEN_VAL, N = EDIM;
        dim3 grid(N / 64, (M + 127) / 128);
        gemm_f16_kernel<__half, true><<<grid, 256, GEMM_SMEM, s2>>>(
            a16, w16 + WOFF_VAL, b_val, v16, M, N);
    }
    cudaEventRecord(evVal, s2);

    // 1b) [s0] [off|attn] = q @ W_oa + b_oa (N = 768, full M)
    {
        int M = BSZ * NQ, N = NOA;
        dim3 grid(N / 64, (M + 127) / 128);
        gemm_f16_kernel<float, false><<<grid, 256, GEMM_SMEM>>>(
            q16, w16 + WOFF_OA, boa, voa, M, N);
    }

    // join v16 into s0
    cudaStreamWaitEvent(0, evVal, 0);

    // 2a) [s0] sampling, batch 0 (qrows [0, NQ)) -> mid16
    sample_kernel<<<NQ, 256>>>(refpts, 0);
    cudaEventRecord(evSampA, 0);

    // 3a) [s2] outA = mid[0:NQ) @ W_out + b_out, overlapped with sampleB
    cudaStreamWaitEvent(s2, evSampA, 0);
    {
        dim3 grid(EDIM / 64, (NQ + 127) / 128);
        gemm_f16_kernel<float, false><<<grid, 256, GEMM_SMEM, s2>>>(
            mid16, w16 + WOFF_OUT, b_out, out, NQ, EDIM);
    }
    cudaEventRecord(evOutA, s2);

    // 2b) [s0] sampling, batch 1 (qrows [NQ, 2*NQ))
    sample_kernel<<<NQ, 256>>>(refpts, NQ);

    // 3b) [s0] outB = mid[NQ:2NQ) @ W_out + b_out
    {
        dim3 grid(EDIM / 64, (NQ + 127) / 128);
        gemm_f16_kernel<float, false><<<grid, 256, GEMM_SMEM>>>(
            mid16 + (size_t)NQ * EDIM, w16 + WOFF_OUT, b_out,
            out + (size_t)NQ * EDIM, NQ, EDIM);
    }

    // join outA back into the capture stream
    cudaStreamWaitEvent(0, evOutA, 0);
}

// round 15
// speedup vs baseline: 1.0418x; 1.0154x over previous
#include <cuda_runtime.h>
#include <cuda_fp16.h>
#include <cstdint>

#define BSZ 2
#define NQ 10000
#define EDIM 256
#define NH 8
#define NL 4
#define NP 8
#define DH 32
#define LEN_VAL 13294
#define NOA 768            // fused off(512) + attn(256) output width

// ---------------- scratch (device globals: allocation-free) ----------------
// v16 layout: [b][h][pos][d] (d=32), +64 pad halfs for the x-pair overfetch
__device__ __half g_v16[(size_t)BSZ * NH * LEN_VAL * DH + 64];
__device__ __half g_a16[(size_t)BSZ * LEN_VAL * EDIM];   // raw value (fp16)
__device__ __half g_q16[(size_t)BSZ * NQ * EDIM];        // q = query + pos (fp16)
__device__ float  g_offattn[(size_t)BSZ * NQ * NOA];     // [off 512 | attn 256]
__device__ __half g_mid16[(size_t)BSZ * NQ * EDIM];      // sampling result (fp16)
__device__ float  g_bias_oa[NOA];

// fp16 weights [K][N], concatenated: [W_val 256x256][W_oa 256x768][W_out 256x256]
#define WOFF_VAL  0
#define WOFF_OA   65536
#define WOFF_OUT  262144
#define WTOTAL    327680
__device__ __half g_W16[WTOTAL];

#define N_VAL_ELEM (BSZ * LEN_VAL * EDIM)   // 6806528
#define N_Q_ELEM   (BSZ * NQ * EDIM)        // 5120000
#define NV4 (N_VAL_ELEM / 4)
#define NQ4 (N_Q_ELEM / 4)
#define PREPQ_THREADS (NQ4 + WTOTAL)

__constant__ int c_Hs[NL]    = {100, 50, 25, 13};
__constant__ int c_Ws[NL]    = {100, 50, 25, 13};
__constant__ int c_start[NL] = {0, 10000, 12500, 13125};

// ---------------- helpers ----------------
__device__ __forceinline__ void ldm_x4(uint32_t& r0, uint32_t& r1, uint32_t& r2, uint32_t& r3,
                                       uint32_t addr) {
    asm volatile("ldmatrix.sync.aligned.m8n8.x4.shared.b16 {%0,%1,%2,%3}, [%4];"
                 : "=r"(r0), "=r"(r1), "=r"(r2), "=r"(r3) : "r"(addr));
}

__device__ __forceinline__ void ldm_x4_trans(uint32_t& r0, uint32_t& r1, uint32_t& r2, uint32_t& r3,
                                             uint32_t addr) {
    asm volatile("ldmatrix.sync.aligned.m8n8.x4.trans.shared.b16 {%0,%1,%2,%3}, [%4];"
                 : "=r"(r0), "=r"(r1), "=r"(r2), "=r"(r3) : "r"(addr));
}

__device__ __forceinline__ void mma_f16(float* d, const uint32_t* a, const uint32_t* b) {
    asm volatile("mma.sync.aligned.m16n8k16.row.col.f32.f16.f16.f32 "
                 "{%0,%1,%2,%3},{%4,%5,%6,%7},{%8,%9},{%0,%1,%2,%3};"
                 : "+f"(d[0]), "+f"(d[1]), "+f"(d[2]), "+f"(d[3])
                 : "r"(a[0]), "r"(a[1]), "r"(a[2]), "r"(a[3]), "r"(b[0]), "r"(b[1]));
}

__device__ __forceinline__ void cp_async16(uint32_t dst, const void* src, bool pred) {
    int sz = pred ? 16 : 0;
    asm volatile("cp.async.cg.shared.global [%0], [%1], 16, %2;\n"
                 :: "r"(dst), "l"(src), "r"(sz));
}
#define CP_COMMIT() asm volatile("cp.async.commit_group;\n" ::)
#define CP_WAIT(N)  asm volatile("cp.async.wait_group %0;\n" :: "n"(N))

__device__ __forceinline__ void store2(float* p, float a, float b) {
    *(float2*)p = make_float2(a, b);
}
__device__ __forceinline__ void store2(__half* p, float a, float b) {
    *(__half2*)p = __floats2half2_rn(a, b);
}

// ---------------- prep kernels (split: q/weights vs value) ----------------
__global__ void prep_q_kernel(const float4* __restrict__ query,
                              const float4* __restrict__ qpos,
                              const float* __restrict__ W_val,
                              const float* __restrict__ W_off,
                              const float* __restrict__ W_attn,
                              const float* __restrict__ W_out,
                              const float* __restrict__ b_off,
                              const float* __restrict__ b_attn) {
    int i = blockIdx.x * blockDim.x + threadIdx.x;
    if (i < NQ4) {
        float4 a = query[i], b = qpos[i];
        ((__half2*)g_q16)[i * 2]     = __floats2half2_rn(a.x + b.x, a.y + b.y);
        ((__half2*)g_q16)[i * 2 + 1] = __floats2half2_rn(a.z + b.z, a.w + b.w);
    } else if (i < PREPQ_THREADS) {
        int j = i - NQ4;
        float x;
        if (j < WOFF_OA) {
            x = W_val[j];
        } else if (j < WOFF_OUT) {
            int k = j - WOFF_OA;
            int r = k / NOA, c = k - r * NOA;
            x = (c < 512) ? W_off[r * 512 + c] : W_attn[r * 256 + (c - 512)];
        } else {
            x = W_out[j - WOFF_OUT];
        }
        g_W16[j] = __float2half(x);
        if (j < NOA) g_bias_oa[j] = (j < 512) ? b_off[j] : b_attn[j - 512];
    }
}

__global__ void prep_val_kernel(const float4* __restrict__ value) {
    int i = blockIdx.x * blockDim.x + threadIdx.x;
    if (i < NV4) {
        float4 v = value[i];
        ((__half2*)g_a16)[i * 2]     = __floats2half2_rn(v.x, v.y);
        ((__half2*)g_a16)[i * 2 + 1] = __floats2half2_rn(v.z, v.w);
    }
}

// ---------------- fp16 tensor-core GEMM, cp.async 4-stage (R10 exact) ----------------
// BM=128, BN=64, BK=32, 256 threads (8 warps 4x2, warp tile 32x32), 2 CTAs/SM.
#define SA_STRIDE 40
#define SB_STRIDE 72
#define SA_BYTES  (128 * SA_STRIDE * 2)   // 10240
#define SB_BYTES  (32 * SB_STRIDE * 2)    // 4608
#define NSTAGE 4
#define OFF_A 0
#define OFF_B (NSTAGE * SA_BYTES)
#define GEMM_SMEM (NSTAGE * (SA_BYTES + SB_BYTES))   // 59392

// PERM=true: C is __half in [b][h][pos][d] layout (value projection)
template <typename TOut, bool PERM>
__global__ void __launch_bounds__(256, 2)
gemm_f16_kernel(const __half* __restrict__ A,
                const __half* __restrict__ B,
                const float* __restrict__ bias,
                TOut* __restrict__ C,
                int M, int N) {
    extern __shared__ char smem_raw[];
    const uint32_t sbase = (uint32_t)__cvta_generic_to_shared(smem_raw);

    const int tid  = threadIdx.x;
    const int lane = tid & 31;
    const int wid  = tid >> 5;
    const int warp_m = wid & 3;       // 0..3
    const int warp_n = wid >> 2;      // 0..1

    const int row0 = blockIdx.y * 128;
    const int col0 = blockIdx.x * 64;

    const int a_row = tid >> 1;             // 0..127
    const int a_c16 = (tid & 1) * 16;       // 0 or 16 halfs
    const int b_kr  = tid >> 3;             // 0..31
    const int b_c8  = (tid & 7) * 8;        // 0..56

    const bool a_pred = (row0 + a_row) < M;
    const __half* srcA = A + (size_t)(row0 + a_row) * 256 + a_c16;
    const __half* srcB = B + (size_t)b_kr * N + col0 + b_c8;

    const uint32_t dA = sbase + OFF_A + a_row * (SA_STRIDE * 2) + a_c16 * 2;
    const uint32_t dB = sbase + OFF_B + b_kr * (SB_STRIDE * 2) + b_c8 * 2;

#define ISSUE(J)                                                             \
    {                                                                        \
        int s = (J) & (NSTAGE - 1);                                          \
        int k0 = (J) * 32;                                                   \
        cp_async16(dA + s * SA_BYTES, srcA + k0, a_pred);                    \
        cp_async16(dA + s * SA_BYTES + 16, srcA + k0 + 8, a_pred);           \
        cp_async16(dB + s * SB_BYTES, srcB + (size_t)k0 * N, true);          \
    }

    ISSUE(0); CP_COMMIT();
    ISSUE(1); CP_COMMIT();
    ISSUE(2); CP_COMMIT();

    float acc[2][4][4];
#pragma unroll
    for (int mt = 0; mt < 2; mt++)
#pragma unroll
        for (int nb = 0; nb < 4; nb++)
#pragma unroll
            for (int j = 0; j < 4; j++) acc[mt][nb][j] = 0.f;

    const int NK = 8;
    for (int it = 0; it < NK; ++it) {
        CP_WAIT(2);
        __syncthreads();
        if (it + 3 < NK) ISSUE(it + 3);
        CP_COMMIT();

        const int s = it & (NSTAGE - 1);
        const uint32_t aB = sbase + OFF_A + s * SA_BYTES;
        const uint32_t bB = sbase + OFF_B + s * SB_BYTES;

#pragma unroll
        for (int ks = 0; ks < 2; ks++) {
            uint32_t af[2][4], bf[4][2];
#pragma unroll
            for (int mt = 0; mt < 2; mt++) {
                int row = warp_m * 32 + mt * 16 + (lane & 15);
                int col = ks * 16 + ((lane >> 4) << 3);
                ldm_x4(af[mt][0], af[mt][1], af[mt][2], af[mt][3],
                       aB + row * (SA_STRIDE * 2) + col * 2);
            }
#pragma unroll
            for (int g = 0; g < 2; g++) {
                int kk = ks * 16 + ((lane >> 3) & 1) * 8 + (lane & 7);
                int nn = warp_n * 32 + g * 16 + ((lane >> 4) & 1) * 8;
                uint32_t r0, r1, r2, r3;
                ldm_x4_trans(r0, r1, r2, r3, bB + kk * (SB_STRIDE * 2) + nn * 2);
                bf[2 * g][0] = r0;     bf[2 * g][1] = r1;
                bf[2 * g + 1][0] = r2; bf[2 * g + 1][1] = r3;
            }
#pragma unroll
            for (int mt = 0; mt < 2; mt++)
#pragma unroll
                for (int nb = 0; nb < 4; nb++)
                    mma_f16(acc[mt][nb], af[mt], bf[nb]);
        }
    }
#undef ISSUE

#pragma unroll
    for (int mt = 0; mt < 2; mt++) {
#pragma unroll
        for (int nb = 0; nb < 4; nb++) {
            int gn = col0 + warp_n * 32 + nb * 8 + (lane & 3) * 2;
            float b0 = bias[gn], b1 = bias[gn + 1];
            int gm0 = row0 + warp_m * 32 + mt * 16 + (lane >> 2);
            int gm1 = gm0 + 8;
            if (PERM) {
                int hh = gn >> 5, dd = gn & 31;
                if (gm0 < M) {
                    int bb = gm0 >= LEN_VAL;
                    int pos = gm0 - bb * LEN_VAL;
                    __half* dst = (__half*)C + ((size_t)(bb * NH + hh) * LEN_VAL + pos) * DH + dd;
                    store2(dst, acc[mt][nb][0] + b0, acc[mt][nb][1] + b1);
                }
                if (gm1 < M) {
                    int bb = gm1 >= LEN_VAL;
                    int pos = gm1 - bb * LEN_VAL;
                    __half* dst = (__half*)C + ((size_t)(bb * NH + hh) * LEN_VAL + pos) * DH + dd;
                    store2(dst, acc[mt][nb][2] + b0, acc[mt][nb][3] + b1);
                }
            } else {
                if (gm0 < M) store2(C + (size_t)gm0 * N + gn,
                                    acc[mt][nb][0] + b0, acc[mt][nb][1] + b1);
                if (gm1 < M) store2(C + (size_t)gm1 * N + gn,
                                    acc[mt][nb][2] + b0, acc[mt][nb][3] + b1);
            }
        }
    }
}

// ---------------- deformable sampling v4 (R10 exact) ----------------
__global__ void __launch_bounds__(256)
sample_kernel(const float* __restrict__ ref) {
    __shared__ int2   s_ad[8][32];
    __shared__ float4 s_w[8][32];

    const int wlocal = threadIdx.x >> 5;
    const int lane   = threadIdx.x & 31;
    const int gw = blockIdx.x * 8 + wlocal;

    const int h = gw & (NH - 1);
    const int n = (gw >> 3) % NQ;
    const int b = gw / (NQ * NH);
    const long qrow = (long)b * NQ + n;
    const float* oa = g_offattn + qrow * NOA;

    // ---- phase 1 ----
    {
        int l = lane >> 3;
        int Hs = c_Hs[l], Ws = c_Ws[l];
        int ocol = ((h * NL + l) * NP + (lane & 7)) * 2;
        float ox = oa[ocol];
        float oy = oa[ocol + 1];
        float rx = ref[(qrow * NL + l) * 2 + 0];
        float ry = ref[(qrow * NL + l) * 2 + 1];

        float x = rx * (float)Ws + ox - 0.5f;
        float y = ry * (float)Hs + oy - 0.5f;

        float fx0 = floorf(x), fy0 = floorf(y);
        int x0 = (int)fx0, y0 = (int)fy0;
        float wx1 = x - fx0, wy1f = y - fy0;
        float wx0 = 1.f - wx1, wy0f = 1.f - wy1f;

        float logit = oa[512 + h * DH + lane];
        float m = logit;
#pragma unroll
        for (int o = 16; o; o >>= 1) m = fmaxf(m, __shfl_xor_sync(0xFFFFFFFFu, m, o));
        float ex = __expf(logit - m);
        float s = ex;
#pragma unroll
        for (int o = 16; o; o >>= 1) s += __shfl_xor_sync(0xFFFFFFFFu, s, o);
        float aw = ex / s;

        int x1 = x0 + 1, y1 = y0 + 1;
        bool vy0 = (y0 >= 0) && (y0 < Hs);
        bool vy1 = (y1 >= 0) && (y1 < Hs);

        int xb = min(max(x0, 0), Ws - 2);
        int pA = xb, pB = xb + 1;
        float wxA = (pA == x0 ? wx0 : 0.f) + (pA == x1 ? wx1 : 0.f);
        float wxB = (pB == x0 ? wx0 : 0.f) + (pB == x1 ? wx1 : 0.f);

        float wy0 = vy0 ? aw * wy0f : 0.f;
        float wy1 = vy1 ? aw * wy1f : 0.f;
        int py0 = vy0 ? y0 : 0;
        int py1 = vy1 ? y1 : 0;

        int base = ((b * NH + h) * LEN_VAL + c_start[l]) * DH;
        int a0 = base + (py0 * Ws + xb) * DH;
        int a1 = base + (py1 * Ws + xb) * DH;

        s_ad[wlocal][lane] = make_int2(a0, a1);
        s_w[wlocal][lane]  = make_float4(wy0 * wxA, wy0 * wxB, wy1 * wxA, wy1 * wxB);
    }
    __syncwarp();

    // ---- phase 2 ----
    const int slot = lane >> 3;
    const int half = (lane >> 2) & 1;
    const int q    = lane & 3;
    const int sub  = half * DH + q * 8;
    const __half* vb = g_v16;

    float2 acc[4];
#pragma unroll
    for (int j = 0; j < 4; j++) acc[j] = make_float2(0.f, 0.f);

#pragma unroll
    for (int it = 0; it < 8; it++) {
        int sIdx = it * 4 + slot;
        int2   ad = s_ad[wlocal][sIdx];
        float4 ww = s_w[wlocal][sIdx];
        float w0 = half ? ww.y : ww.x;
        float w1 = half ? ww.w : ww.z;

        uint4 u0 = *(const uint4*)(vb + ad.x + sub);
        uint4 u1 = *(const uint4*)(vb + ad.y + sub);
        float2 f;
        f = __half22float2(*(__half2*)&u0.x); acc[0].x = fmaf(w0, f.x, acc[0].x); acc[0].y = fmaf(w0, f.y, acc[0].y);
        f = __half22float2(*(__half2*)&u0.y); acc[1].x = fmaf(w0, f.x, acc[1].x); acc[1].y = fmaf(w0, f.y, acc[1].y);
        f = __half22float2(*(__half2*)&u0.z); acc[2].x = fmaf(w0, f.x, acc[2].x); acc[2].y = fmaf(w0, f.y, acc[2].y);
        f = __half22float2(*(__half2*)&u0.w); acc[3].x = fmaf(w0, f.x, acc[3].x); acc[3].y = fmaf(w0, f.y, acc[3].y);
        f = __half22float2(*(__half2*)&u1.x); acc[0].x = fmaf(w1, f.x, acc[0].x); acc[0].y = fmaf(w1, f.y, acc[0].y);
        f = __half22float2(*(__half2*)&u1.y); acc[1].x = fmaf(w1, f.x, acc[1].x); acc[1].y = fmaf(w1, f.y, acc[1].y);
        f = __half22float2(*(__half2*)&u1.z); acc[2].x = fmaf(w1, f.x, acc[2].x); acc[2].y = fmaf(w1, f.y, acc[2].y);
        f = __half22float2(*(__half2*)&u1.w); acc[3].x = fmaf(w1, f.x, acc[3].x); acc[3].y = fmaf(w1, f.y, acc[3].y);
    }

#pragma unroll
    for (int o = 4; o <= 16; o <<= 1) {
#pragma unroll
        for (int j = 0; j < 4; j++) {
            acc[j].x += __shfl_xor_sync(0xFFFFFFFFu, acc[j].x, o);
            acc[j].y += __shfl_xor_sync(0xFFFFFFFFu, acc[j].y, o);
        }
    }

    if (lane < 4) {
        __align__(16) __half2 outv[4];
#pragma unroll
        for (int j = 0; j < 4; j++) outv[j] = __floats2half2_rn(acc[j].x, acc[j].y);
        size_t midx = qrow * EDIM + h * DH + lane * 8;
        *(uint4*)(g_mid16 + midx) = *(uint4*)outv;
    }
}

// ---------------- launch: R10 schedule with split prep ----------------
extern "C" void kernel_launch(void* const* d_in, const int* in_sizes, int n_in,
                              void* d_out, int out_size) {
    const float* query   = (const float*)d_in[0];
    const float* value   = (const float*)d_in[1];
    const float* qpos    = (const float*)d_in[2];
    const float* refpts  = (const float*)d_in[3];
    const float* W_off   = (const float*)d_in[5];
    const float* b_off   = (const float*)d_in[6];
    const float* W_attn  = (const float*)d_in[7];
    const float* b_attn  = (const float*)d_in[8];
    const float* W_val   = (const float*)d_in[9];
    const float* b_val   = (const float*)d_in[10];
    const float* W_out   = (const float*)d_in[11];
    const float* b_out   = (const float*)d_in[12];
    float* out = (float*)d_out;

    __half *w16, *q16, *a16, *v16, *mid16;
    float *voa, *boa;
    cudaGetSymbolAddress((void**)&w16, g_W16);
    cudaGetSymbolAddress((void**)&q16, g_q16);
    cudaGetSymbolAddress((void**)&a16, g_a16);
    cudaGetSymbolAddress((void**)&v16, g_v16);
    cudaGetSymbolAddress((void**)&mid16, g_mid16);
    cudaGetSymbolAddress((void**)&voa, g_offattn);
    cudaGetSymbolAddress((void**)&boa, g_bias_oa);

    static bool init_done = false;
    static cudaStream_t s2;
    static cudaEvent_t evStart, evVal;
    if (!init_done) {
        cudaFuncSetAttribute((const void*)gemm_f16_kernel<float, false>,
                             cudaFuncAttributeMaxDynamicSharedMemorySize, GEMM_SMEM);
        cudaFuncSetAttribute((const void*)gemm_f16_kernel<__half, true>,
                             cudaFuncAttributeMaxDynamicSharedMemorySize, GEMM_SMEM);
        cudaStreamCreateWithFlags(&s2, cudaStreamNonBlocking);
        cudaEventCreateWithFlags(&evStart, cudaEventDisableTiming);
        cudaEventCreateWithFlags(&evVal,   cudaEventDisableTiming);
        init_done = true;
    }

    // fork s2 at t=0 (empty event: both streams start immediately)
    cudaEventRecord(evStart, 0);
    cudaStreamWaitEvent(s2, evStart, 0);

    // [s2] value -> fp16, then value projection GEMM (permuted output)
    prep_val_kernel<<<(NV4 + 255) / 256, 256, 0, s2>>>((const float4*)value);
    {
        int M = BSZ * LEN_VAL, N = EDIM;
        dim3 grid(N / 64, (M + 127) / 128);
        gemm_f16_kernel<__half, true><<<grid, 256, GEMM_SMEM, s2>>>(
            a16, w16 + WOFF_VAL, b_val, v16, M, N);
    }
    cudaEventRecord(evVal, s2);

    // [s0] q/weights prep, then oa GEMM
    prep_q_kernel<<<(PREPQ_THREADS + 255) / 256, 256>>>(
        (const float4*)query, (const float4*)qpos,
        W_val, W_off, W_attn, W_out, b_off, b_attn);
    {
        int M = BSZ * NQ, N = NOA;
        dim3 grid(N / 64, (M + 127) / 128);
        gemm_f16_kernel<float, false><<<grid, 256, GEMM_SMEM>>>(
            q16, w16 + WOFF_OA, boa, voa, M, N);
    }

    // join v16 into s0
    cudaStreamWaitEvent(0, evVal, 0);

    // [s0] deformable sampling -> g_mid16
    {
        int groups = BSZ * NQ * NH;              // 160000
        sample_kernel<<<groups / 8, 256>>>(refpts);
    }
    // [s0] out = mid @ W_out + b_out
    {
        int M = BSZ * NQ, N = EDIM;
        dim3 grid(N / 64, (M + 127) / 128);
        gemm_f16_kernel<float, false><<<grid, 256, GEMM_SMEM>>>(
            mid16, w16 + WOFF_OUT, b_out, out, M, N);
    }
}

// round 16
// speedup vs baseline: 1.0434x; 1.0015x over previous
#include <cuda_runtime.h>
#include <cuda_fp16.h>
#include <cstdint>

#define BSZ 2
#define NQ 10000
#define EDIM 256
#define NH 8
#define NL 4
#define NP 8
#define DH 32
#define LEN_VAL 13294
#define NOA 768            // fused off(512) + attn(256) output width

#define NPIX   (BSZ * NH * LEN_VAL)          // 212704 pixels
#define VHALF  ((size_t)NPIX * DH)           // halfs in copyA = 6806528
#define OFFB   ((int)(VHALF + 64))           // copyB base (128B aligned)

// ---------------- scratch (device globals: allocation-free) ----------------
// v16: [copyA: pixel p at p*32][pad 64][copyB: pixel p at OFFB+(p-1)*32][tail pad]
__device__ __half g_v16[2 * VHALF + 192];
__device__ __half g_a16[(size_t)BSZ * LEN_VAL * EDIM];   // raw value (fp16)
__device__ __half g_q16[(size_t)BSZ * NQ * EDIM];        // q = query + pos (fp16)
__device__ float  g_offattn[(size_t)BSZ * NQ * NOA];     // [off 512 | attn 256]
__device__ __half g_mid16[(size_t)BSZ * NQ * EDIM];      // sampling result (fp16)
__device__ float  g_bias_oa[NOA];

// fp16 weights [K][N], concatenated: [W_val 256x256][W_oa 256x768][W_out 256x256]
#define WOFF_VAL  0
#define WOFF_OA   65536
#define WOFF_OUT  262144
#define WTOTAL    327680
__device__ __half g_W16[WTOTAL];

#define N_VAL_ELEM (BSZ * LEN_VAL * EDIM)   // 6806528
#define N_Q_ELEM   (BSZ * NQ * EDIM)        // 5120000
#define NV4 (N_VAL_ELEM / 4)
#define NQ4 (N_Q_ELEM / 4)
#define PREP_THREADS (NV4 + NQ4 + WTOTAL)

__constant__ int c_Hs[NL]    = {100, 50, 25, 13};
__constant__ int c_Ws[NL]    = {100, 50, 25, 13};
__constant__ int c_start[NL] = {0, 10000, 12500, 13125};

// ---------------- helpers ----------------
__device__ __forceinline__ void ldm_x4(uint32_t& r0, uint32_t& r1, uint32_t& r2, uint32_t& r3,
                                       uint32_t addr) {
    asm volatile("ldmatrix.sync.aligned.m8n8.x4.shared.b16 {%0,%1,%2,%3}, [%4];"
                 : "=r"(r0), "=r"(r1), "=r"(r2), "=r"(r3) : "r"(addr));
}

__device__ __forceinline__ void ldm_x4_trans(uint32_t& r0, uint32_t& r1, uint32_t& r2, uint32_t& r3,
                                             uint32_t addr) {
    asm volatile("ldmatrix.sync.aligned.m8n8.x4.trans.shared.b16 {%0,%1,%2,%3}, [%4];"
                 : "=r"(r0), "=r"(r1), "=r"(r2), "=r"(r3) : "r"(addr));
}

__device__ __forceinline__ void mma_f16(float* d, const uint32_t* a, const uint32_t* b) {
    asm volatile("mma.sync.aligned.m16n8k16.row.col.f32.f16.f16.f32 "
                 "{%0,%1,%2,%3},{%4,%5,%6,%7},{%8,%9},{%0,%1,%2,%3};"
                 : "+f"(d[0]), "+f"(d[1]), "+f"(d[2]), "+f"(d[3])
                 : "r"(a[0]), "r"(a[1]), "r"(a[2]), "r"(a[3]), "r"(b[0]), "r"(b[1]));
}

__device__ __forceinline__ void cp_async16(uint32_t dst, const void* src, bool pred) {
    int sz = pred ? 16 : 0;
    asm volatile("cp.async.cg.shared.global [%0], [%1], 16, %2;\n"
                 :: "r"(dst), "l"(src), "r"(sz));
}
#define CP_COMMIT() asm volatile("cp.async.commit_group;\n" ::)
#define CP_WAIT(N)  asm volatile("cp.async.wait_group %0;\n" :: "n"(N))

__device__ __forceinline__ void store2(float* p, float a, float b) {
    *(float2*)p = make_float2(a, b);
}
__device__ __forceinline__ void store2(__half* p, float a, float b) {
    *(__half2*)p = __floats2half2_rn(a, b);
}

// ---------------- fused prep kernel (R10 exact) ----------------
__global__ void prep_kernel(const float4* __restrict__ value,
                            const float4* __restrict__ query,
                            const float4* __restrict__ qpos,
                            const float* __restrict__ W_val,
                            const float* __restrict__ W_off,
                            const float* __restrict__ W_attn,
                            const float* __restrict__ W_out,
                            const float* __restrict__ b_off,
                            const float* __restrict__ b_attn) {
    int i = blockIdx.x * blockDim.x + threadIdx.x;
    if (i < NV4) {
        float4 v = value[i];
        ((__half2*)g_a16)[i * 2]     = __floats2half2_rn(v.x, v.y);
        ((__half2*)g_a16)[i * 2 + 1] = __floats2half2_rn(v.z, v.w);
    } else if (i < NV4 + NQ4) {
        int j = i - NV4;
        float4 a = query[j], b = qpos[j];
        ((__half2*)g_q16)[j * 2]     = __floats2half2_rn(a.x + b.x, a.y + b.y);
        ((__half2*)g_q16)[j * 2 + 1] = __floats2half2_rn(a.z + b.z, a.w + b.w);
    } else if (i < PREP_THREADS) {
        int j = i - NV4 - NQ4;
        float x;
        if (j < WOFF_OA) {
            x = W_val[j];
        } else if (j < WOFF_OUT) {
            int k = j - WOFF_OA;
            int r = k / NOA, c = k - r * NOA;
            x = (c < 512) ? W_off[r * 512 + c] : W_attn[r * 256 + (c - 512)];
        } else {
            x = W_out[j - WOFF_OUT];
        }
        g_W16[j] = __float2half(x);
        if (j < NOA) g_bias_oa[j] = (j < 512) ? b_off[j] : b_attn[j - 512];
    }
}

// ---------------- fp16 tensor-core GEMM, cp.async 4-stage (R10 core) ----------------
// BM=128, BN=64, BK=32, 256 threads (8 warps 4x2, warp tile 32x32), 2 CTAs/SM.
#define SA_STRIDE 40
#define SB_STRIDE 72
#define SA_BYTES  (128 * SA_STRIDE * 2)   // 10240
#define SB_BYTES  (32 * SB_STRIDE * 2)    // 4608
#define NSTAGE 4
#define OFF_A 0
#define OFF_B (NSTAGE * SA_BYTES)
#define GEMM_SMEM (NSTAGE * (SA_BYTES + SB_BYTES))   // 59392

// PERM=true: C is __half, dual-copy [b][h][pos][d] layout (value projection)
template <typename TOut, bool PERM>
__global__ void __launch_bounds__(256, 2)
gemm_f16_kernel(const __half* __restrict__ A,
                const __half* __restrict__ B,
                const float* __restrict__ bias,
                TOut* __restrict__ C,
                int M, int N) {
    extern __shared__ char smem_raw[];
    const uint32_t sbase = (uint32_t)__cvta_generic_to_shared(smem_raw);

    const int tid  = threadIdx.x;
    const int lane = tid & 31;
    const int wid  = tid >> 5;
    const int warp_m = wid & 3;       // 0..3
    const int warp_n = wid >> 2;      // 0..1

    const int row0 = blockIdx.y * 128;
    const int col0 = blockIdx.x * 64;

    const int a_row = tid >> 1;             // 0..127
    const int a_c16 = (tid & 1) * 16;       // 0 or 16 halfs
    const int b_kr  = tid >> 3;             // 0..31
    const int b_c8  = (tid & 7) * 8;        // 0..56

    const bool a_pred = (row0 + a_row) < M;
    const __half* srcA = A + (size_t)(row0 + a_row) * 256 + a_c16;
    const __half* srcB = B + (size_t)b_kr * N + col0 + b_c8;

    const uint32_t dA = sbase + OFF_A + a_row * (SA_STRIDE * 2) + a_c16 * 2;
    const uint32_t dB = sbase + OFF_B + b_kr * (SB_STRIDE * 2) + b_c8 * 2;

#define ISSUE(J)                                                             \
    {                                                                        \
        int s = (J) & (NSTAGE - 1);                                          \
        int k0 = (J) * 32;                                                   \
        cp_async16(dA + s * SA_BYTES, srcA + k0, a_pred);                    \
        cp_async16(dA + s * SA_BYTES + 16, srcA + k0 + 8, a_pred);           \
        cp_async16(dB + s * SB_BYTES, srcB + (size_t)k0 * N, true);          \
    }

    ISSUE(0); CP_COMMIT();
    ISSUE(1); CP_COMMIT();
    ISSUE(2); CP_COMMIT();

    float acc[2][4][4];
#pragma unroll
    for (int mt = 0; mt < 2; mt++)
#pragma unroll
        for (int nb = 0; nb < 4; nb++)
#pragma unroll
            for (int j = 0; j < 4; j++) acc[mt][nb][j] = 0.f;

    const int NK = 8;
    for (int it = 0; it < NK; ++it) {
        CP_WAIT(2);
        __syncthreads();
        if (it + 3 < NK) ISSUE(it + 3);
        CP_COMMIT();

        const int s = it & (NSTAGE - 1);
        const uint32_t aB = sbase + OFF_A + s * SA_BYTES;
        const uint32_t bB = sbase + OFF_B + s * SB_BYTES;

#pragma unroll
        for (int ks = 0; ks < 2; ks++) {
            uint32_t af[2][4], bf[4][2];
#pragma unroll
            for (int mt = 0; mt < 2; mt++) {
                int row = warp_m * 32 + mt * 16 + (lane & 15);
                int col = ks * 16 + ((lane >> 4) << 3);
                ldm_x4(af[mt][0], af[mt][1], af[mt][2], af[mt][3],
                       aB + row * (SA_STRIDE * 2) + col * 2);
            }
#pragma unroll
            for (int g = 0; g < 2; g++) {
                int kk = ks * 16 + ((lane >> 3) & 1) * 8 + (lane & 7);
                int nn = warp_n * 32 + g * 16 + ((lane >> 4) & 1) * 8;
                uint32_t r0, r1, r2, r3;
                ldm_x4_trans(r0, r1, r2, r3, bB + kk * (SB_STRIDE * 2) + nn * 2);
                bf[2 * g][0] = r0;     bf[2 * g][1] = r1;
                bf[2 * g + 1][0] = r2; bf[2 * g + 1][1] = r3;
            }
#pragma unroll
            for (int mt = 0; mt < 2; mt++)
#pragma unroll
                for (int nb = 0; nb < 4; nb++)
                    mma_f16(acc[mt][nb], af[mt], bf[nb]);
        }
    }
#undef ISSUE

#pragma unroll
    for (int mt = 0; mt < 2; mt++) {
#pragma unroll
        for (int nb = 0; nb < 4; nb++) {
            int gn = col0 + warp_n * 32 + nb * 8 + (lane & 3) * 2;
            float b0 = bias[gn], b1 = bias[gn + 1];
            int gm0 = row0 + warp_m * 32 + mt * 16 + (lane >> 2);
            int gm1 = gm0 + 8;
            if (PERM) {
                int hh = gn >> 5, dd = gn & 31;
                if (gm0 < M) {
                    int bb = gm0 >= LEN_VAL;
                    int pos = gm0 - bb * LEN_VAL;
                    size_t pi = (size_t)(bb * NH + hh) * LEN_VAL + pos;
                    __half* d1 = (__half*)C + pi * DH + dd;
                    store2(d1, acc[mt][nb][0] + b0, acc[mt][nb][1] + b1);
                    __half* d2 = (__half*)C + (VHALF + 32) + pi * DH + dd;
                    store2(d2, acc[mt][nb][0] + b0, acc[mt][nb][1] + b1);
                }
                if (gm1 < M) {
                    int bb = gm1 >= LEN_VAL;
                    int pos = gm1 - bb * LEN_VAL;
                    size_t pi = (size_t)(bb * NH + hh) * LEN_VAL + pos;
                    __half* d1 = (__half*)C + pi * DH + dd;
                    store2(d1, acc[mt][nb][2] + b0, acc[mt][nb][3] + b1);
                    __half* d2 = (__half*)C + (VHALF + 32) + pi * DH + dd;
                    store2(d2, acc[mt][nb][2] + b0, acc[mt][nb][3] + b1);
                }
            } else {
                if (gm0 < M) store2(C + (size_t)gm0 * N + gn,
                                    acc[mt][nb][0] + b0, acc[mt][nb][1] + b1);
                if (gm1 < M) store2(C + (size_t)gm1 * N + gn,
                                    acc[mt][nb][2] + b0, acc[mt][nb][3] + b1);
            }
        }
    }
}

// ---------------- deformable sampling v6: parity-aligned pair fetch ----------------
// Identical to R10 v4 except the pair address selects copyA (even pair start)
// or copyB (odd pair start) so every 128B pair fetch hits exactly one L1 line.
__global__ void __launch_bounds__(256)
sample_kernel(const float* __restrict__ ref) {
    __shared__ int2   s_ad[8][32];
    __shared__ float4 s_w[8][32];

    const int wlocal = threadIdx.x >> 5;
    const int lane   = threadIdx.x & 31;
    const int gw = blockIdx.x * 8 + wlocal;

    const int h = gw & (NH - 1);
    const int n = (gw >> 3) % NQ;
    const int b = gw / (NQ * NH);
    const long qrow = (long)b * NQ + n;
    const float* oa = g_offattn + qrow * NOA;

    // ---- phase 1 ----
    {
        int l = lane >> 3;
        int Hs = c_Hs[l], Ws = c_Ws[l];
        int ocol = ((h * NL + l) * NP + (lane & 7)) * 2;
        float ox = oa[ocol];
        float oy = oa[ocol + 1];
        float rx = ref[(qrow * NL + l) * 2 + 0];
        float ry = ref[(qrow * NL + l) * 2 + 1];

        float x = rx * (float)Ws + ox - 0.5f;
        float y = ry * (float)Hs + oy - 0.5f;

        float fx0 = floorf(x), fy0 = floorf(y);
        int x0 = (int)fx0, y0 = (int)fy0;
        float wx1 = x - fx0, wy1f = y - fy0;
        float wx0 = 1.f - wx1, wy0f = 1.f - wy1f;

        float logit = oa[512 + h * DH + lane];
        float m = logit;
#pragma unroll
        for (int o = 16; o; o >>= 1) m = fmaxf(m, __shfl_xor_sync(0xFFFFFFFFu, m, o));
        float ex = __expf(logit - m);
        float s = ex;
#pragma unroll
        for (int o = 16; o; o >>= 1) s += __shfl_xor_sync(0xFFFFFFFFu, s, o);
        float aw = ex / s;

        int x1 = x0 + 1, y1 = y0 + 1;
        bool vy0 = (y0 >= 0) && (y0 < Hs);
        bool vy1 = (y1 >= 0) && (y1 < Hs);

        int xb = min(max(x0, 0), Ws - 2);
        int pA = xb, pB = xb + 1;
        float wxA = (pA == x0 ? wx0 : 0.f) + (pA == x1 ? wx1 : 0.f);
        float wxB = (pB == x0 ? wx0 : 0.f) + (pB == x1 ? wx1 : 0.f);

        float wy0 = vy0 ? aw * wy0f : 0.f;
        float wy1 = vy1 ? aw * wy1f : 0.f;
        int py0 = vy0 ? y0 : 0;
        int py1 = vy1 ? y1 : 0;

        int brow = (b * NH + h) * LEN_VAL + c_start[l];
        int pix0 = brow + py0 * Ws + xb;
        int pix1 = brow + py1 * Ws + xb;
        // aligned pair address: even start -> copyA, odd start -> copyB
        int a0 = ((pix0 & ~1) << 5) + ((pix0 & 1) ? OFFB : 0);
        int a1 = ((pix1 & ~1) << 5) + ((pix1 & 1) ? OFFB : 0);

        s_ad[wlocal][lane] = make_int2(a0, a1);
        s_w[wlocal][lane]  = make_float4(wy0 * wxA, wy0 * wxB, wy1 * wxA, wy1 * wxB);
    }
    __syncwarp();

    // ---- phase 2 ----
    const int slot = lane >> 3;
    const int half = (lane >> 2) & 1;
    const int q    = lane & 3;
    const int sub  = half * DH + q * 8;
    const __half* vb = g_v16;

    float2 acc[4];
#pragma unroll
    for (int j = 0; j < 4; j++) acc[j] = make_float2(0.f, 0.f);

#pragma unroll
    for (int it = 0; it < 8; it++) {
        int sIdx = it * 4 + slot;
        int2   ad = s_ad[wlocal][sIdx];
        float4 ww = s_w[wlocal][sIdx];
        float w0 = half ? ww.y : ww.x;
        float w1 = half ? ww.w : ww.z;

        uint4 u0 = *(const uint4*)(vb + ad.x + sub);
        uint4 u1 = *(const uint4*)(vb + ad.y + sub);
        float2 f;
        f = __half22float2(*(__half2*)&u0.x); acc[0].x = fmaf(w0, f.x, acc[0].x); acc[0].y = fmaf(w0, f.y, acc[0].y);
        f = __half22float2(*(__half2*)&u0.y); acc[1].x = fmaf(w0, f.x, acc[1].x); acc[1].y = fmaf(w0, f.y, acc[1].y);
        f = __half22float2(*(__half2*)&u0.z); acc[2].x = fmaf(w0, f.x, acc[2].x); acc[2].y = fmaf(w0, f.y, acc[2].y);
        f = __half22float2(*(__half2*)&u0.w); acc[3].x = fmaf(w0, f.x, acc[3].x); acc[3].y = fmaf(w0, f.y, acc[3].y);
        f = __half22float2(*(__half2*)&u1.x); acc[0].x = fmaf(w1, f.x, acc[0].x); acc[0].y = fmaf(w1, f.y, acc[0].y);
        f = __half22float2(*(__half2*)&u1.y); acc[1].x = fmaf(w1, f.x, acc[1].x); acc[1].y = fmaf(w1, f.y, acc[1].y);
        f = __half22float2(*(__half2*)&u1.z); acc[2].x = fmaf(w1, f.x, acc[2].x); acc[2].y = fmaf(w1, f.y, acc[2].y);
        f = __half22float2(*(__half2*)&u1.w); acc[3].x = fmaf(w1, f.x, acc[3].x); acc[3].y = fmaf(w1, f.y, acc[3].y);
    }

#pragma unroll
    for (int o = 4; o <= 16; o <<= 1) {
#pragma unroll
        for (int j = 0; j < 4; j++) {
            acc[j].x += __shfl_xor_sync(0xFFFFFFFFu, acc[j].x, o);
            acc[j].y += __shfl_xor_sync(0xFFFFFFFFu, acc[j].y, o);
        }
    }

    if (lane < 4) {
        __align__(16) __half2 outv[4];
#pragma unroll
        for (int j = 0; j < 4; j++) outv[j] = __floats2half2_rn(acc[j].x, acc[j].y);
        size_t midx = qrow * EDIM + h * DH + lane * 8;
        *(uint4*)(g_mid16 + midx) = *(uint4*)outv;
    }
}

// ---------------- launch (R10 schedule exact) ----------------
extern "C" void kernel_launch(void* const* d_in, const int* in_sizes, int n_in,
                              void* d_out, int out_size) {
    const float* query   = (const float*)d_in[0];
    const float* value   = (const float*)d_in[1];
    const float* qpos    = (const float*)d_in[2];
    const float* refpts  = (const float*)d_in[3];
    const float* W_off   = (const float*)d_in[5];
    const float* b_off   = (const float*)d_in[6];
    const float* W_attn  = (const float*)d_in[7];
    const float* b_attn  = (const float*)d_in[8];
    const float* W_val   = (const float*)d_in[9];
    const float* b_val   = (const float*)d_in[10];
    const float* W_out   = (const float*)d_in[11];
    const float* b_out   = (const float*)d_in[12];
    float* out = (float*)d_out;

    __half *w16, *q16, *a16, *v16, *mid16;
    float *voa, *boa;
    cudaGetSymbolAddress((void**)&w16, g_W16);
    cudaGetSymbolAddress((void**)&q16, g_q16);
    cudaGetSymbolAddress((void**)&a16, g_a16);
    cudaGetSymbolAddress((void**)&v16, g_v16);
    cudaGetSymbolAddress((void**)&mid16, g_mid16);
    cudaGetSymbolAddress((void**)&voa, g_offattn);
    cudaGetSymbolAddress((void**)&boa, g_bias_oa);

    static bool init_done = false;
    static cudaStream_t s2;
    static cudaEvent_t evPrep, evVal;
    if (!init_done) {
        cudaFuncSetAttribute((const void*)gemm_f16_kernel<float, false>,
                             cudaFuncAttributeMaxDynamicSharedMemorySize, GEMM_SMEM);
        cudaFuncSetAttribute((const void*)gemm_f16_kernel<__half, true>,
                             cudaFuncAttributeMaxDynamicSharedMemorySize, GEMM_SMEM);
        cudaStreamCreateWithFlags(&s2, cudaStreamNonBlocking);
        cudaEventCreateWithFlags(&evPrep, cudaEventDisableTiming);
        cudaEventCreateWithFlags(&evVal, cudaEventDisableTiming);
        init_done = true;
    }

    // 0) fused prep (vectorized)
    prep_kernel<<<(PREP_THREADS + 255) / 256, 256>>>(
        (const float4*)value, (const float4*)query, (const float4*)qpos,
        W_val, W_off, W_attn, W_out, b_off, b_attn);

    // fork: value-projection chain on s2
    cudaEventRecord(evPrep, 0);
    cudaStreamWaitEvent(s2, evPrep, 0);

    // 1a) [s2] v = value @ W_val + b_val -> fp16 dual-copy [b][h][pos][d]
    {
        int M = BSZ * LEN_VAL, N = EDIM;
        dim3 grid(N / 64, (M + 127) / 128);
        gemm_f16_kernel<__half, true><<<grid, 256, GEMM_SMEM, s2>>>(
            a16, w16 + WOFF_VAL, b_val, v16, M, N);
    }
    cudaEventRecord(evVal, s2);

    // 1b) [default] [off|attn] = q @ W_oa + b_oa (N = 768)
    {
        int M = BSZ * NQ, N = NOA;
        dim3 grid(N / 64, (M + 127) / 128);
        gemm_f16_kernel<float, false><<<grid, 256, GEMM_SMEM>>>(
            q16, w16 + WOFF_OA, boa, voa, M, N);
    }

    // join
    cudaStreamWaitEvent(0, evVal, 0);

    // 2) deformable sampling -> g_mid16
    {
        int groups = BSZ * NQ * NH;              // 160000
        sample_kernel<<<groups / 8, 256>>>(refpts);
    }
    // 3) out = mid @ W_out + b_out
    {
        int M = BSZ * NQ, N = EDIM;
        dim3 grid(N / 64, (M + 127) / 128);
        gemm_f16_kernel<float, false><<<grid, 256, GEMM_SMEM>>>(
            mid16, w16 + WOFF_OUT, b_out, out, M, N);
    }
}